// round 1
// baseline (speedup 1.0000x reference)
#include <cuda_runtime.h>
#include <math.h>

// Problem constants
#define NB 16      // batch
#define CC 64      // channels
#define TT 64      // time
#define VV 25      // vertices
#define HH 4       // heads
#define DD 64      // head dim
#define LL (TT*VV) // 1600 tokens
#define HD (HH*DD) // 256

// Scratch (device globals; no runtime allocation allowed)
__device__ float g_q[NB*HH*LL*DD];
__device__ float g_k[NB*HH*LL*DD];
__device__ float g_v[NB*HH*LL*DD];
__device__ float g_o[NB*HD*LL];   // attention out in [N, H*D, T, V] layout
__device__ float g_y[NB*CC*LL];   // after out_nets (conv+bn1+res+relu)

// ---------------------------------------------------------------------------
// Kernel 1: QKV projection.  out[l, j] = sum_c x_l[l, c] * W[c, j] + b[j]
// x is NCHW [N,64,64,25]; row l of x_l is contiguous per channel (stride L).
// Writes q/k/v in [N,H,L,D] layout.
// Grid: (12 col tiles, 400 row tiles), 256 threads, 64x64 tile, K=64.
// ---------------------------------------------------------------------------
__global__ void qkv_kernel(const float* __restrict__ x,
                           const float* __restrict__ Wq,
                           const float* __restrict__ bq) {
    __shared__ float Xs[64 * 65];   // [row_local][c]
    __shared__ float Ws[64 * 65];   // [c][col_local]
    const int bx = blockIdx.x;      // col tile (0..11)
    const int by = blockIdx.y;      // row tile (0..399)
    const int tid = threadIdx.x;

    const int row_base = by * 64;           // 1600 % 64 == 0 -> n fixed per block
    const int n  = row_base / LL;
    const int l0 = row_base % LL;

    const float* xb = x + (size_t)n * CC * LL + l0;
#pragma unroll
    for (int it = 0; it < 16; it++) {
        int idx = tid + it * 256;
        int c = idx >> 6, ll = idx & 63;
        Xs[ll * 65 + c] = xb[c * LL + ll];          // coalesced over ll
    }
    const float* wb = Wq + bx * 64;
#pragma unroll
    for (int it = 0; it < 16; it++) {
        int idx = tid + it * 256;
        int c = idx >> 6, j = idx & 63;
        Ws[c * 65 + j] = wb[c * 768 + j];           // coalesced over j
    }
    __syncthreads();

    const int ty = tid >> 4, tx = tid & 15;
    float acc[4][4] = {};
#pragma unroll
    for (int kk = 0; kk < 64; kk++) {
        float a[4], b[4];
#pragma unroll
        for (int i = 0; i < 4; i++) a[i] = Xs[(ty * 4 + i) * 65 + kk];
#pragma unroll
        for (int j = 0; j < 4; j++) b[j] = Ws[kk * 65 + tx * 4 + j];
#pragma unroll
        for (int i = 0; i < 4; i++)
#pragma unroll
            for (int j = 0; j < 4; j++) acc[i][j] = fmaf(a[i], b[j], acc[i][j]);
    }

    // col block bx covers j in [bx*64, bx*64+64): part = bx/4, head = bx%4
    const int part = bx >> 2;
    const int h    = bx & 3;
    float* outp = (part == 0) ? g_q : (part == 1) ? g_k : g_v;
#pragma unroll
    for (int i = 0; i < 4; i++) {
        int l = l0 + ty * 4 + i;
#pragma unroll
        for (int j = 0; j < 4; j++) {
            int d = tx * 4 + j;
            float vvv = acc[i][j] + bq[bx * 64 + d];
            outp[((size_t)(n * HH + h) * LL + l) * DD + d] = vvv;
        }
    }
}

// ---------------------------------------------------------------------------
// Kernel 2: flash-style attention. Block = 64 query rows of one (n,h).
// Streams K/V in 64-row chunks, online softmax, O in registers.
// Writes g_o in [N, H*D, T, V] layout (l = t*V+v contiguous).
// Grid: (25 qtiles, 64 nh), 256 threads.
// Dynamic smem: Qs,Ks,Vs,Ps [64][65] + stats.
// ---------------------------------------------------------------------------
extern __shared__ float attn_sm[];
__global__ void attn_kernel() {
    float* Qs  = attn_sm;
    float* Ks  = Qs + 64 * 65;
    float* Vs  = Ks + 64 * 65;
    float* Ps  = Vs + 64 * 65;
    float* m_s = Ps + 64 * 65;
    float* l_s = m_s + 64;
    float* al_s = l_s + 64;

    const int qb = blockIdx.x;
    const int nh = blockIdx.y;
    const int tid = threadIdx.x;

    const float* qp  = g_q + ((size_t)nh * LL + qb * 64) * DD;
    const float* kp0 = g_k + (size_t)nh * LL * DD;
    const float* vp0 = g_v + (size_t)nh * LL * DD;

#pragma unroll
    for (int it = 0; it < 16; it++) {
        int idx = tid + it * 256;
        int r = idx >> 6, d = idx & 63;
        Qs[r * 65 + d] = qp[r * DD + d] * 0.125f;   // 1/sqrt(64)
    }
    if (tid < 64) { m_s[tid] = -1e30f; l_s[tid] = 0.f; }

    const int ty = tid >> 4, tx = tid & 15;
    float oacc[4][4] = {};

    for (int kb = 0; kb < 25; kb++) {
        __syncthreads();   // Qs/stats ready (iter 0); prev O-update done (iter>0)
        const float* kp = kp0 + (size_t)kb * 64 * DD;
        const float* vp = vp0 + (size_t)kb * 64 * DD;
#pragma unroll
        for (int it = 0; it < 16; it++) {
            int idx = tid + it * 256;
            int r = idx >> 6, d = idx & 63;
            Ks[r * 65 + d] = kp[r * DD + d];
            Vs[r * 65 + d] = vp[r * DD + d];
        }
        __syncthreads();

        // S = Qs @ Ks^T  (scores already scaled via Qs)
        float s[4][4] = {};
#pragma unroll
        for (int kk = 0; kk < 64; kk++) {
            float a[4], b[4];
#pragma unroll
            for (int i = 0; i < 4; i++) a[i] = Qs[(ty * 4 + i) * 65 + kk];
#pragma unroll
            for (int j = 0; j < 4; j++) b[j] = Ks[(tx * 4 + j) * 65 + kk];
#pragma unroll
            for (int i = 0; i < 4; i++)
#pragma unroll
                for (int j = 0; j < 4; j++) s[i][j] = fmaf(a[i], b[j], s[i][j]);
        }
#pragma unroll
        for (int i = 0; i < 4; i++)
#pragma unroll
            for (int j = 0; j < 4; j++)
                Ps[(ty * 4 + i) * 65 + tx * 4 + j] = s[i][j];
        __syncthreads();

        // online softmax row stats (one thread per row)
        if (tid < 64) {
            int r = tid;
            float rm = m_s[r];
#pragma unroll 8
            for (int c = 0; c < 64; c++) rm = fmaxf(rm, Ps[r * 65 + c]);
            float al = __expf(m_s[r] - rm);
            float ps = 0.f;
#pragma unroll 8
            for (int c = 0; c < 64; c++) {
                float p = __expf(Ps[r * 65 + c] - rm);
                Ps[r * 65 + c] = p;
                ps += p;
            }
            m_s[r] = rm;
            l_s[r] = l_s[r] * al + ps;
            al_s[r] = al;
        }
        __syncthreads();

        // O = O*alpha + P @ V
        float alv[4];
#pragma unroll
        for (int i = 0; i < 4; i++) alv[i] = al_s[ty * 4 + i];
#pragma unroll
        for (int i = 0; i < 4; i++)
#pragma unroll
            for (int j = 0; j < 4; j++) oacc[i][j] *= alv[i];
#pragma unroll
        for (int kk = 0; kk < 64; kk++) {
            float p[4], b[4];
#pragma unroll
            for (int i = 0; i < 4; i++) p[i] = Ps[(ty * 4 + i) * 65 + kk];
#pragma unroll
            for (int j = 0; j < 4; j++) b[j] = Vs[kk * 65 + tx * 4 + j];
#pragma unroll
            for (int i = 0; i < 4; i++)
#pragma unroll
                for (int j = 0; j < 4; j++) oacc[i][j] = fmaf(p[i], b[j], oacc[i][j]);
        }
    }

    const int n = nh >> 2, h = nh & 3;
#pragma unroll
    for (int i = 0; i < 4; i++) {
        int l = qb * 64 + ty * 4 + i;
        float inv = 1.f / l_s[ty * 4 + i];
#pragma unroll
        for (int j = 0; j < 4; j++) {
            int d = tx * 4 + j;
            g_o[((size_t)(n * HD) + h * DD + d) * LL + l] = oacc[i][j] * inv;
        }
    }
}

// ---------------------------------------------------------------------------
// Kernel 3: (1,9) conv (256->64 ch) as implicit-im2col GEMM
//   M=64 (out ch), N=25600 (n*t*v), K=2304 (256 ci * 9 kw)
// Fused: +bias, BN1, +x residual, relu -> g_y
// Grid: 400 blocks (spatial tiles of 64), 256 threads, Ktile=32.
// ---------------------------------------------------------------------------
__global__ void conv_kernel(const float* __restrict__ x,
                            const float* __restrict__ W,
                            const float* __restrict__ bias,
                            const float* __restrict__ g1,
                            const float* __restrict__ be1,
                            const float* __restrict__ mu1,
                            const float* __restrict__ va1) {
    __shared__ float As[64 * 33];   // weights [c][k_local]
    __shared__ float Bs[32 * 65];   // im2col  [k_local][s_local]
    const int tid = threadIdx.x;
    const int sbase = blockIdx.x * 64;
    const int ty = tid >> 4, tx = tid & 15;

    float acc[4][4] = {};
    for (int kb = 0; kb < 72; kb++) {
        const int kbase = kb * 32;
#pragma unroll
        for (int it = 0; it < 8; it++) {           // load A: 2048 elems
            int idx = tid + it * 256;
            int c = idx >> 5, kl = idx & 31;
            As[c * 33 + kl] = W[c * 2304 + kbase + kl];   // coalesced over kl
        }
#pragma unroll
        for (int it = 0; it < 8; it++) {           // load B: 2048 elems
            int idx = tid + it * 256;
            int kl = idx >> 6, sl = idx & 63;
            int k = kbase + kl;
            int ci = k / 9, kw = k - ci * 9;
            int s = sbase + sl;
            int n = s / LL;
            int rem = s - n * LL;
            int t = rem / VV;
            int v = rem - t * VV;
            int vi = v + kw - 4;
            float val = 0.f;
            if (vi >= 0 && vi < VV)
                val = g_o[((size_t)(n * HD + ci)) * LL + t * VV + vi];
            Bs[kl * 65 + sl] = val;
        }
        __syncthreads();
#pragma unroll
        for (int kk = 0; kk < 32; kk++) {
            float a[4], b[4];
#pragma unroll
            for (int i = 0; i < 4; i++) a[i] = As[(ty * 4 + i) * 33 + kk];
#pragma unroll
            for (int j = 0; j < 4; j++) b[j] = Bs[kk * 65 + tx * 4 + j];
#pragma unroll
            for (int i = 0; i < 4; i++)
#pragma unroll
                for (int j = 0; j < 4; j++) acc[i][j] = fmaf(a[i], b[j], acc[i][j]);
        }
        __syncthreads();
    }

    // epilogue: bn1((conv + bias)) + x, relu
#pragma unroll
    for (int i = 0; i < 4; i++) {
        int c = ty * 4 + i;
        float inv = g1[c] * rsqrtf(va1[c] + 1e-5f);
        float add = be1[c] - mu1[c] * inv + bias[c] * inv;
#pragma unroll
        for (int j = 0; j < 4; j++) {
            int s = sbase + tx * 4 + j;
            int n = s / LL;
            int rem = s - n * LL;
            size_t addr = ((size_t)(n * CC + c)) * LL + rem;
            float val = acc[i][j] * inv + add + x[addr];
            g_y[addr] = fmaxf(val, 0.f);
        }
    }
}

// ---------------------------------------------------------------------------
// Kernel 4: 1x1 conv (64->64) + BN2 + residual(y) + relu -> d_out
// Grid: 400 blocks (spatial tiles of 64), 256 threads, K=64 one shot.
// ---------------------------------------------------------------------------
__global__ void ff_kernel(const float* __restrict__ Wff,
                          const float* __restrict__ bff,
                          const float* __restrict__ g2,
                          const float* __restrict__ be2,
                          const float* __restrict__ mu2,
                          const float* __restrict__ va2,
                          float* __restrict__ out) {
    __shared__ float Ws[64 * 65];   // W[c][ci]
    __shared__ float Ys[64 * 65];   // y[ci][s_local]
    const int tid = threadIdx.x;
    const int sbase = blockIdx.x * 64;
    const int n  = sbase / LL;          // 1600 % 64 == 0
    const int lo = sbase % LL;

#pragma unroll
    for (int it = 0; it < 16; it++) {
        int idx = tid + it * 256;
        int c = idx >> 6, ci = idx & 63;
        Ws[c * 65 + ci] = Wff[c * 64 + ci];
    }
    const float* yb = g_y + (size_t)n * CC * LL + lo;
#pragma unroll
    for (int it = 0; it < 16; it++) {
        int idx = tid + it * 256;
        int ci = idx >> 6, sl = idx & 63;
        Ys[ci * 65 + sl] = yb[ci * LL + sl];
    }
    __syncthreads();

    const int ty = tid >> 4, tx = tid & 15;
    float acc[4][4] = {};
#pragma unroll
    for (int kk = 0; kk < 64; kk++) {
        float a[4], b[4];
#pragma unroll
        for (int i = 0; i < 4; i++) a[i] = Ws[(ty * 4 + i) * 65 + kk];
#pragma unroll
        for (int j = 0; j < 4; j++) b[j] = Ys[kk * 65 + tx * 4 + j];
#pragma unroll
        for (int i = 0; i < 4; i++)
#pragma unroll
            for (int j = 0; j < 4; j++) acc[i][j] = fmaf(a[i], b[j], acc[i][j]);
    }

#pragma unroll
    for (int i = 0; i < 4; i++) {
        int c = ty * 4 + i;
        float inv = g2[c] * rsqrtf(va2[c] + 1e-5f);
        float add = be2[c] - mu2[c] * inv + bff[c] * inv;
#pragma unroll
        for (int j = 0; j < 4; j++) {
            int sl = tx * 4 + j;
            float resid = Ys[c * 65 + sl];
            float val = acc[i][j] * inv + add + resid;
            out[((size_t)(n * CC + c)) * LL + lo + sl] = fmaxf(val, 0.f);
        }
    }
}

// ---------------------------------------------------------------------------
extern "C" void kernel_launch(void* const* d_in, const int* in_sizes, int n_in,
                              void* d_out, int out_size) {
    const float* x     = (const float*)d_in[0];
    const float* W_qkv = (const float*)d_in[1];
    const float* b_qkv = (const float*)d_in[2];
    const float* W_out = (const float*)d_in[3];
    const float* b_out = (const float*)d_in[4];
    const float* g1    = (const float*)d_in[5];
    const float* be1   = (const float*)d_in[6];
    const float* mu1   = (const float*)d_in[7];
    const float* va1   = (const float*)d_in[8];
    const float* W_ff  = (const float*)d_in[9];
    const float* b_ff  = (const float*)d_in[10];
    const float* g2    = (const float*)d_in[11];
    const float* be2   = (const float*)d_in[12];
    const float* mu2   = (const float*)d_in[13];
    const float* va2   = (const float*)d_in[14];
    float* out = (float*)d_out;

    const int ATTN_SMEM = (4 * 64 * 65 + 3 * 64) * (int)sizeof(float);  // 67328 B
    cudaFuncSetAttribute(attn_kernel,
                         cudaFuncAttributeMaxDynamicSharedMemorySize, ATTN_SMEM);

    qkv_kernel<<<dim3(12, 400), 256>>>(x, W_qkv, b_qkv);
    attn_kernel<<<dim3(25, 64), 256, ATTN_SMEM>>>();
    conv_kernel<<<400, 256>>>(x, W_out, b_out, g1, be1, mu1, va1);
    ff_kernel<<<400, 256>>>(W_ff, b_ff, g2, be2, mu2, va2, out);
}